// round 12
// baseline (speedup 1.0000x reference)
#include <cuda_runtime.h>
#include <cuda_fp16.h>
#include <cstdint>
#include <math.h>

#define BATCH 256
#define SEQL  196
#define CDIM  768
#define KCODE 2048
#define MTOT  (BATCH*SEQL)   // 50176

// ---------------------------------------------------------------------------
// scratch (no cudaMalloc allowed)
// ---------------------------------------------------------------------------
__device__ float  g_codeNorm[KCODE];
__device__ int    g_idx[MTOT];
__device__ int    g_cand[MTOT * 4];
__device__ float  g_att[MTOT];
__device__ float  g_mask[MTOT];
__device__ __half g_Ahi[(size_t)MTOT * CDIM];   // 77 MB
__device__ __half g_Bhi[(size_t)KCODE * CDIM];  // 3.1 MB

// ---------------------------------------------------------------------------
// helpers
// ---------------------------------------------------------------------------
__device__ __forceinline__ uint32_t smem_u32(const void* p) {
    uint32_t a;
    asm("{ .reg .u64 t; cvta.to.shared.u64 t, %1; cvt.u32.u64 %0, t; }"
        : "=r"(a) : "l"(p));
    return a;
}

__device__ __forceinline__ void cp16(uint32_t saddr, const void* gaddr) {
    asm volatile("cp.async.ca.shared.global [%0], [%1], 16;"
                 :: "r"(saddr), "l"(gaddr));
}
#define CP_COMMIT() asm volatile("cp.async.commit_group;" ::: "memory")
#define CP_WAIT2()  asm volatile("cp.async.wait_group 2;" ::: "memory")
#define CP_WAIT0()  asm volatile("cp.async.wait_group 0;" ::: "memory")

__device__ __forceinline__ void ldsm_x4(uint32_t& r0, uint32_t& r1,
                                        uint32_t& r2, uint32_t& r3,
                                        uint32_t addr) {
    asm volatile("ldmatrix.sync.aligned.m8n8.x4.shared.b16 {%0,%1,%2,%3}, [%4];"
                 : "=r"(r0), "=r"(r1), "=r"(r2), "=r"(r3) : "r"(addr));
}

__device__ __forceinline__ void mma16816(float& c0, float& c1, float& c2, float& c3,
                                         uint32_t a0, uint32_t a1, uint32_t a2, uint32_t a3,
                                         uint32_t b0, uint32_t b1) {
    asm volatile("mma.sync.aligned.m16n8k16.row.col.f32.f16.f16.f32 "
                 "{%0,%1,%2,%3}, {%4,%5,%6,%7}, {%8,%9}, {%0,%1,%2,%3};"
                 : "+f"(c0), "+f"(c1), "+f"(c2), "+f"(c3)
                 : "r"(a0), "r"(a1), "r"(a2), "r"(a3), "r"(b0), "r"(b1));
}

// ---------------------------------------------------------------------------
// convert: float -> fp16 hi only
// ---------------------------------------------------------------------------
__global__ void convert_A_kernel(const float* __restrict__ src, int n4) {
    int i = blockIdx.x * blockDim.x + threadIdx.x;
    if (i >= n4) return;
    float4 v = reinterpret_cast<const float4*>(src)[i];
    __half2* hp = reinterpret_cast<__half2*>(g_Ahi) + 2 * (size_t)i;
    hp[0] = __halves2half2(__float2half_rn(v.x), __float2half_rn(v.y));
    hp[1] = __halves2half2(__float2half_rn(v.z), __float2half_rn(v.w));
}

__global__ void convert_B_kernel(const float* __restrict__ src, int n4) {
    int i = blockIdx.x * blockDim.x + threadIdx.x;
    if (i >= n4) return;
    float4 v = reinterpret_cast<const float4*>(src)[i];
    __half2* hp = reinterpret_cast<__half2*>(g_Bhi) + 2 * (size_t)i;
    hp[0] = __halves2half2(__float2half_rn(v.x), __float2half_rn(v.y));
    hp[1] = __halves2half2(__float2half_rn(v.z), __float2half_rn(v.w));
}

// ---------------------------------------------------------------------------
// codebook row norms ||e||^2 (fp32 exact)
// ---------------------------------------------------------------------------
__global__ void codenorm_kernel(const float* __restrict__ cb) {
    int k = blockIdx.x;
    const float* row = cb + (size_t)k * CDIM;
    float s = 0.f;
    for (int c = threadIdx.x; c < CDIM; c += blockDim.x) {
        float v = row[c];
        s += v * v;
    }
    for (int o = 16; o; o >>= 1) s += __shfl_down_sync(0xffffffffu, s, o);
    __shared__ float red[8];
    int lane = threadIdx.x & 31, wid = threadIdx.x >> 5;
    if (lane == 0) red[wid] = s;
    __syncthreads();
    if (threadIdx.x == 0) {
        float t = 0.f;
        for (int w = 0; w < (int)(blockDim.x >> 5); w++) t += red[w];
        g_codeNorm[k] = t;
    }
}

// ---------------------------------------------------------------------------
// Phase 1: approximate distance GEMM (hi x hi only) + top-4 candidate select.
// CTA: 128 threads = 4 warps (1M x 4N), tile 64(M) x 256(N), warp tile 64x64.
// 4-stage cp.async pipeline, lookahead 2, issue-before-wait, one sync/step.
// Each thread keeps best-2 per owned row-slot; per-row reduce picks the top-4
// of 32 (by (d, idx)) into g_cand. Phase 2 re-ranks those exactly in fp64.
// ---------------------------------------------------------------------------
#define LDAB   48                   // bytes per SMEM row (16 halfs + 8 pad)
#define AMAT_B (64 * LDAB)          // 3072
#define BMAT_B (256 * LDAB)         // 12288
#define OFF_AH 0
#define OFF_BH (AMAT_B)
#define STAGE_B (AMAT_B + BMAT_B)   // 15360
#define NSTAGE  4
#define SMEM_B  (NSTAGE * STAGE_B)  // 61440
#define KSTEPS  (CDIM / 16)         // 48
#define NTILES  (KCODE / 256)       // 8
#define LOOKAHEAD 2

__global__ void __launch_bounds__(128, 2) vq_hmma_kernel() {
    extern __shared__ char smem[];
    const uint32_t sb = smem_u32(smem);

    const int tid   = threadIdx.x;
    const int lane  = tid & 31;
    const int warpN = tid >> 5;        // 0..3
    const int tg    = lane & 3;        // 0..3
    const int grp8  = lane >> 2;       // 0..7
    const int m0    = blockIdx.x * 64;

    // cp.async mapping: thread -> 5 x 16B chunks (1 A chunk + 4 B chunks)
    const int ldRow  = tid >> 1;       // 0..63
    const int ldHalf = tid & 1;        // 0..1
    const uint32_t aOff = (uint32_t)(ldRow * LDAB + ldHalf * 16);
    const __half* AhiBase = g_Ahi + (size_t)(m0 + ldRow) * CDIM + ldHalf * 8;
    uint32_t bOff[4];
    size_t   bG[4];
#pragma unroll
    for (int r = 0; r < 4; r++) {
        bOff[r] = (uint32_t)((ldRow + r * 64) * LDAB + ldHalf * 16);
        bG[r]   = (size_t)(ldRow + r * 64) * CDIM + ldHalf * 8;
    }

    // ldmatrix addresses (within a stage, relative)
    const uint32_t aRowOff =
        (uint32_t)((lane & 15) * LDAB + (lane >> 4) * 16);
    const uint32_t bRowOff =
        (uint32_t)((warpN * 64 + ((lane >> 4) << 3) + (lane & 7)) * LDAB +
                   ((lane >> 3) & 1) * 16);

    // per-thread best-2 argmin per owned row-slot (4 mf x 2 halves = 8 slots)
    float b1[8], b2[8];
    int   i1[8], i2[8];
#pragma unroll
    for (int i = 0; i < 8; i++) {
        b1[i] = 3.4e38f; b2[i] = 3.4e38f; i1[i] = 0x7FFFFFFF; i2[i] = 0x7FFFFFFF;
    }

    // issue cursor
    int in = 0, ik = 0;

    // prologue: issue data steps 0..LOOKAHEAD-1
#pragma unroll
    for (int p = 0; p < LOOKAHEAD; p++) {
        uint32_t st = sb + (uint32_t)p * STAGE_B;
        int gk = ik * 16;
        const __half* bh0 = g_Bhi + (size_t)in * 256 * CDIM;
        cp16(st + OFF_AH + aOff, AhiBase + gk);
#pragma unroll
        for (int r = 0; r < 4; r++)
            cp16(st + OFF_BH + bOff[r], bh0 + bG[r] + gk);
        CP_COMMIT();
        if (++ik == KSTEPS) { ik = 0; in++; }
    }

    for (int nt = 0; nt < NTILES; nt++) {
        const int n0 = nt * 256;

        float acc[4][8][4];
#pragma unroll
        for (int mf = 0; mf < 4; mf++)
#pragma unroll
            for (int nf = 0; nf < 8; nf++)
#pragma unroll
                for (int c = 0; c < 4; c++) acc[mf][nf][c] = 0.f;

        for (int ks = 0; ks < KSTEPS; ks++) {
            const int g = nt * KSTEPS + ks;

            // issue data g+2 into stage (g+2)%4 BEFORE the wait.
            // That stage was consumed between barriers g-2 and g-1; all warps
            // passed barrier g-1 -> safe to refill pre-barrier.
            if (in < NTILES) {
                uint32_t st = sb +
                    (uint32_t)((g + LOOKAHEAD) & (NSTAGE - 1)) * STAGE_B;
                int gk = ik * 16;
                const __half* bh0 = g_Bhi + (size_t)in * 256 * CDIM;
                cp16(st + OFF_AH + aOff, AhiBase + gk);
#pragma unroll
                for (int r = 0; r < 4; r++)
                    cp16(st + OFF_BH + bOff[r], bh0 + bG[r] + gk);
                if (++ik == KSTEPS) { ik = 0; in++; }
            }
            CP_COMMIT();   // unconditional: keeps group counting exact at tail

            CP_WAIT2();
            __syncthreads();

            const uint32_t stage = sb + (uint32_t)(g & (NSTAGE - 1)) * STAGE_B;

            uint32_t ah[4][4];
#pragma unroll
            for (int mf = 0; mf < 4; mf++) {
                uint32_t a = stage + aRowOff + (uint32_t)(mf * 16 * LDAB);
                ldsm_x4(ah[mf][0], ah[mf][1], ah[mf][2], ah[mf][3], a + OFF_AH);
            }

#pragma unroll
            for (int h = 0; h < 2; h++) {
                uint32_t bh[4][2];
#pragma unroll
                for (int p = 0; p < 2; p++) {
                    uint32_t b = stage + bRowOff +
                                 (uint32_t)((h * 32 + p * 16) * LDAB);
                    uint32_t r0, r1, r2, r3;
                    ldsm_x4(r0, r1, r2, r3, b + OFF_BH);
                    bh[p * 2][0] = r0; bh[p * 2][1] = r1;
                    bh[p * 2 + 1][0] = r2; bh[p * 2 + 1][1] = r3;
                }
#pragma unroll
                for (int mf = 0; mf < 4; mf++) {
#pragma unroll
                    for (int nf = 0; nf < 4; nf++) {
                        float* c = acc[mf][h * 4 + nf];
                        mma16816(c[0], c[1], c[2], c[3],
                                 ah[mf][0], ah[mf][1], ah[mf][2], ah[mf][3],
                                 bh[nf][0], bh[nf][1]);
                    }
                }
            }
        }

        // fold this n-tile into running best-2 (ascending n => first-occurrence)
#pragma unroll
        for (int nf = 0; nf < 8; nf++) {
            int n = n0 + warpN * 64 + nf * 8 + tg * 2;
            float cn0 = __ldg(&g_codeNorm[n]);
            float cn1 = __ldg(&g_codeNorm[n + 1]);
#pragma unroll
            for (int mf = 0; mf < 4; mf++) {
                float d0 = cn0 - 2.f * acc[mf][nf][0];
                float d1 = cn1 - 2.f * acc[mf][nf][1];
                float d2 = cn0 - 2.f * acc[mf][nf][2];
                float d3 = cn1 - 2.f * acc[mf][nf][3];
                int s0 = 2 * mf, s1 = 2 * mf + 1;
                if (d0 < b1[s0]) { b2[s0]=b1[s0]; i2[s0]=i1[s0]; b1[s0]=d0; i1[s0]=n; }
                else if (d0 < b2[s0]) { b2[s0]=d0; i2[s0]=n; }
                if (d1 < b1[s0]) { b2[s0]=b1[s0]; i2[s0]=i1[s0]; b1[s0]=d1; i1[s0]=n+1; }
                else if (d1 < b2[s0]) { b2[s0]=d1; i2[s0]=n+1; }
                if (d2 < b1[s1]) { b2[s1]=b1[s1]; i2[s1]=i1[s1]; b1[s1]=d2; i1[s1]=n; }
                else if (d2 < b2[s1]) { b2[s1]=d2; i2[s1]=n; }
                if (d3 < b1[s1]) { b2[s1]=b1[s1]; i2[s1]=i1[s1]; b1[s1]=d3; i1[s1]=n+1; }
                else if (d3 < b2[s1]) { b2[s1]=d3; i2[s1]=n+1; }
            }
        }
    }

    // drain remaining (empty) groups before reusing smem
    CP_WAIT0();
    __syncthreads();

    // per-row candidate pool: 16 owner threads x (best1, best2) = 32 entries
    float* sV = reinterpret_cast<float*>(smem);            // [64][32]
    int*   sI = reinterpret_cast<int*>(smem + 64 * 32 * 4);
    const int slot = warpN * 4 + tg;
#pragma unroll
    for (int mf = 0; mf < 4; mf++) {
        int r0 = mf * 16 + grp8;
        sV[r0 * 32 + slot]        = b1[2 * mf];
        sI[r0 * 32 + slot]        = i1[2 * mf];
        sV[r0 * 32 + slot + 16]   = b2[2 * mf];
        sI[r0 * 32 + slot + 16]   = i2[2 * mf];
        sV[(r0+8) * 32 + slot]      = b1[2 * mf + 1];
        sI[(r0+8) * 32 + slot]      = i1[2 * mf + 1];
        sV[(r0+8) * 32 + slot + 16] = b2[2 * mf + 1];
        sI[(r0+8) * 32 + slot + 16] = i2[2 * mf + 1];
    }
    __syncthreads();
    if (tid < 64) {
        float td[4] = {3.4e38f, 3.4e38f, 3.4e38f, 3.4e38f};
        int   ti[4] = {0x7FFFFFFF, 0x7FFFFFFF, 0x7FFFFFFF, 0x7FFFFFFF};
        for (int e = 0; e < 32; e++) {
            float v = sV[tid * 32 + e];
            int   id = sI[tid * 32 + e];
#pragma unroll
            for (int k = 0; k < 4; k++) {
                if (v < td[k] || (v == td[k] && id < ti[k])) {
                    for (int j = 3; j > k; j--) { td[j]=td[j-1]; ti[j]=ti[j-1]; }
                    td[k] = v; ti[k] = id;
                    break;
                }
            }
        }
#pragma unroll
        for (int c = 0; c < 4; c++) g_cand[(m0 + tid) * 4 + c] = ti[c];
    }
}

// ---------------------------------------------------------------------------
// Phase 2: exact fp64 re-rank of the 4 candidates per token. One warp/token.
// d = sum (x_i - e_i)^2 in double; min with idx tie-break -> g_idx.
// ---------------------------------------------------------------------------
__global__ void refine_kernel(const float* __restrict__ in,
                              const float* __restrict__ cb) {
    int w    = (blockIdx.x * blockDim.x + threadIdx.x) >> 5;
    int lane = threadIdx.x & 31;
    if (w >= MTOT) return;
    const float* xr = in + (size_t)w * CDIM;
    float x[24];
#pragma unroll
    for (int i = 0; i < 24; i++) x[i] = xr[lane + 32 * i];

    double bd = 1e300;
    int    bi = 0x7FFFFFFF;
#pragma unroll
    for (int c = 0; c < 4; c++) {
        int idx = g_cand[w * 4 + c];
        const float* er = cb + (size_t)idx * CDIM;
        double s = 0.0;
#pragma unroll
        for (int i = 0; i < 24; i++) {
            double df = (double)x[i] - (double)er[lane + 32 * i];
            s = fma(df, df, s);
        }
#pragma unroll
        for (int o = 16; o; o >>= 1) s += __shfl_xor_sync(0xffffffffu, s, o);
        if (s < bd || (s == bd && idx < bi)) { bd = s; bi = idx; }
    }
    if (lane == 0) g_idx[w] = bi;
}

// ---------------------------------------------------------------------------
// att[t] = relu(dot(codebook[idx[t]], att_w[:,1])), + idx written as float
// ---------------------------------------------------------------------------
__global__ void att_kernel(const float* __restrict__ cb,
                           const float* __restrict__ att_w,
                           float* __restrict__ out_idx_f, int write_idx) {
    int gw   = (blockIdx.x * blockDim.x + threadIdx.x) >> 5;
    int lane = threadIdx.x & 31;
    if (gw >= MTOT) return;
    int idx = g_idx[gw];
    const float* row = cb + (size_t)idx * CDIM;
    float s = 0.f;
    for (int c = lane; c < CDIM; c += 32)
        s = fmaf(row[c], att_w[c * 3 + 1], s);
    for (int o = 16; o; o >>= 1) s += __shfl_down_sync(0xffffffffu, s, o);
    if (lane == 0) {
        g_att[gw] = fmaxf(s, 0.f);
        if (write_idx) out_idx_f[gw] = (float)idx;
    }
}

// ---------------------------------------------------------------------------
// softmax over L per batch -> g_mask
// ---------------------------------------------------------------------------
__global__ void softmax_kernel() {
    int b = blockIdx.x;
    int t = threadIdx.x;
    __shared__ float red[8];
    float v = (t < SEQL) ? g_att[b * SEQL + t] : -3.4e38f;

    float m = v;
    for (int o = 16; o; o >>= 1) m = fmaxf(m, __shfl_xor_sync(0xffffffffu, m, o));
    int lane = t & 31, wid = t >> 5;
    if (lane == 0) red[wid] = m;
    __syncthreads();
    if (wid == 0) {
        float x = (lane < 8) ? red[lane] : -3.4e38f;
        for (int o = 4; o; o >>= 1) x = fmaxf(x, __shfl_xor_sync(0xffffffffu, x, o));
        if (lane == 0) red[0] = x;
    }
    __syncthreads();
    float bmax = red[0];
    __syncthreads();

    float e = (t < SEQL) ? __expf(v - bmax) : 0.f;
    float s = e;
    for (int o = 16; o; o >>= 1) s += __shfl_xor_sync(0xffffffffu, s, o);
    if (lane == 0) red[wid] = s;
    __syncthreads();
    if (wid == 0) {
        float x = (lane < 8) ? red[lane] : 0.f;
        for (int o = 4; o; o >>= 1) x += __shfl_xor_sync(0xffffffffu, x, o);
        if (lane == 0) red[0] = x;
    }
    __syncthreads();
    float bsum = red[0];
    if (t < SEQL) g_mask[b * SEQL + t] = e / bsum;
}

// ---------------------------------------------------------------------------
// out[t,c] = codebook[idx[t]][c] + in[t,c] * mask[t]
// ---------------------------------------------------------------------------
__global__ void out_kernel(const float* __restrict__ in,
                           const float* __restrict__ cb,
                           float* __restrict__ out) {
    int t  = blockIdx.x;
    int c4 = threadIdx.x;          // 0..191
    float m = g_mask[t];
    int idx = g_idx[t];
    const float4* q4 = reinterpret_cast<const float4*>(cb + (size_t)idx * CDIM);
    const float4* x4 = reinterpret_cast<const float4*>(in + (size_t)t * CDIM);
    float4* o4 = reinterpret_cast<float4*>(out + (size_t)t * CDIM);
    float4 q = q4[c4];
    float4 x = x4[c4];
    o4[c4] = make_float4(fmaf(x.x, m, q.x), fmaf(x.y, m, q.y),
                         fmaf(x.z, m, q.z), fmaf(x.w, m, q.w));
}

// ---------------------------------------------------------------------------
extern "C" void kernel_launch(void* const* d_in, const int* in_sizes, int n_in,
                              void* d_out, int out_size) {
    const float* in_feas  = (const float*)d_in[0];   // [B, L, C]
    const float* codebook = (const float*)d_in[1];   // [K, C]
    const float* att_w    = (const float*)d_in[2];   // [1, C, 3]
    float* out = (float*)d_out;
    (void)in_sizes; (void)n_in;

    int write_idx = (out_size >= MTOT * CDIM + MTOT) ? 1 : 0;
    float* out_idx_f = out + (size_t)MTOT * CDIM;

    cudaFuncSetAttribute(vq_hmma_kernel,
                         cudaFuncAttributeMaxDynamicSharedMemorySize, SMEM_B);

    {
        int n4 = MTOT * CDIM / 4;   // 9,633,792
        convert_A_kernel<<<(n4 + 255) / 256, 256>>>(in_feas, n4);
    }
    {
        int n4 = KCODE * CDIM / 4;  // 393,216
        convert_B_kernel<<<(n4 + 255) / 256, 256>>>(codebook, n4);
    }
    codenorm_kernel<<<KCODE, 256>>>(codebook);

    vq_hmma_kernel<<<MTOT / 64, 128, SMEM_B>>>();
    refine_kernel<<<(MTOT * 32 + 255) / 256, 256>>>(in_feas, codebook);

    att_kernel<<<(MTOT * 32 + 255) / 256, 256>>>(codebook, att_w, out_idx_f, write_idx);
    softmax_kernel<<<BATCH, 256>>>();
    out_kernel<<<MTOT, CDIM / 4>>>(in_feas, codebook, out);
}

// round 13
// speedup vs baseline: 2.0068x; 2.0068x over previous
#include <cuda_runtime.h>
#include <cuda_fp16.h>
#include <cstdint>
#include <math.h>

#define BATCH 256
#define SEQL  196
#define CDIM  768
#define KCODE 2048
#define MTOT  (BATCH*SEQL)   // 50176

// ---------------------------------------------------------------------------
// scratch (no cudaMalloc allowed)
// ---------------------------------------------------------------------------
__device__ float  g_codeNorm[KCODE];
__device__ int    g_idx[MTOT];
__device__ int    g_cand[MTOT * 4];
__device__ float  g_att[MTOT];
__device__ float  g_mask[MTOT];
__device__ __half g_Ahi[(size_t)MTOT * CDIM];   // 77 MB
__device__ __half g_Bhi[(size_t)KCODE * CDIM];  // 3.1 MB

// ---------------------------------------------------------------------------
// helpers
// ---------------------------------------------------------------------------
__device__ __forceinline__ uint32_t smem_u32(const void* p) {
    uint32_t a;
    asm("{ .reg .u64 t; cvta.to.shared.u64 t, %1; cvt.u32.u64 %0, t; }"
        : "=r"(a) : "l"(p));
    return a;
}

__device__ __forceinline__ void cp16(uint32_t saddr, const void* gaddr) {
    asm volatile("cp.async.ca.shared.global [%0], [%1], 16;"
                 :: "r"(saddr), "l"(gaddr));
}
#define CP_COMMIT() asm volatile("cp.async.commit_group;" ::: "memory")
#define CP_WAIT1()  asm volatile("cp.async.wait_group 1;" ::: "memory")
#define CP_WAIT0()  asm volatile("cp.async.wait_group 0;" ::: "memory")

__device__ __forceinline__ void ldsm_x4(uint32_t& r0, uint32_t& r1,
                                        uint32_t& r2, uint32_t& r3,
                                        uint32_t addr) {
    asm volatile("ldmatrix.sync.aligned.m8n8.x4.shared.b16 {%0,%1,%2,%3}, [%4];"
                 : "=r"(r0), "=r"(r1), "=r"(r2), "=r"(r3) : "r"(addr));
}

__device__ __forceinline__ void mma16816(float& c0, float& c1, float& c2, float& c3,
                                         uint32_t a0, uint32_t a1, uint32_t a2, uint32_t a3,
                                         uint32_t b0, uint32_t b1) {
    asm volatile("mma.sync.aligned.m16n8k16.row.col.f32.f16.f16.f32 "
                 "{%0,%1,%2,%3}, {%4,%5,%6,%7}, {%8,%9}, {%0,%1,%2,%3};"
                 : "+f"(c0), "+f"(c1), "+f"(c2), "+f"(c3)
                 : "r"(a0), "r"(a1), "r"(a2), "r"(a3), "r"(b0), "r"(b1));
}

// ---------------------------------------------------------------------------
// convert: float -> fp16 hi only
// ---------------------------------------------------------------------------
__global__ void convert_A_kernel(const float* __restrict__ src, int n4) {
    int i = blockIdx.x * blockDim.x + threadIdx.x;
    if (i >= n4) return;
    float4 v = reinterpret_cast<const float4*>(src)[i];
    __half2* hp = reinterpret_cast<__half2*>(g_Ahi) + 2 * (size_t)i;
    hp[0] = __halves2half2(__float2half_rn(v.x), __float2half_rn(v.y));
    hp[1] = __halves2half2(__float2half_rn(v.z), __float2half_rn(v.w));
}

__global__ void convert_B_kernel(const float* __restrict__ src, int n4) {
    int i = blockIdx.x * blockDim.x + threadIdx.x;
    if (i >= n4) return;
    float4 v = reinterpret_cast<const float4*>(src)[i];
    __half2* hp = reinterpret_cast<__half2*>(g_Bhi) + 2 * (size_t)i;
    hp[0] = __halves2half2(__float2half_rn(v.x), __float2half_rn(v.y));
    hp[1] = __halves2half2(__float2half_rn(v.z), __float2half_rn(v.w));
}

// ---------------------------------------------------------------------------
// codebook row norms ||e||^2 (fp32 exact)
// ---------------------------------------------------------------------------
__global__ void codenorm_kernel(const float* __restrict__ cb) {
    int k = blockIdx.x;
    const float* row = cb + (size_t)k * CDIM;
    float s = 0.f;
    for (int c = threadIdx.x; c < CDIM; c += blockDim.x) {
        float v = row[c];
        s += v * v;
    }
    for (int o = 16; o; o >>= 1) s += __shfl_down_sync(0xffffffffu, s, o);
    __shared__ float red[8];
    int lane = threadIdx.x & 31, wid = threadIdx.x >> 5;
    if (lane == 0) red[wid] = s;
    __syncthreads();
    if (threadIdx.x == 0) {
        float t = 0.f;
        for (int w = 0; w < (int)(blockDim.x >> 5); w++) t += red[w];
        g_codeNorm[k] = t;
    }
}

// ---------------------------------------------------------------------------
// Phase 1: approximate distance GEMM (hi x hi) + top-4 candidate select.
// CTA: 128 threads = 4 warps (1M x 4N), tile 64(M) x 256(N), warp tile 64x64.
// k-step 32 (two 16-k sub-steps per barrier) -> 192 barriers total.
// 3-stage cp.async pipeline, lookahead 1, issue-before-wait, one sync/step.
// Each thread keeps best-2 per owned row-slot; per-row reduce picks top-4
// of 32 (by (d, idx)) into g_cand; phase 2 re-ranks exactly in fp32.
// ---------------------------------------------------------------------------
#define LDAB   48                   // bytes per SMEM row (16 halfs + 8 pad)
#define AMAT_B (64 * LDAB)          // 3072
#define BMAT_B (256 * LDAB)         // 12288
#define OFF_AH 0
#define OFF_BH (AMAT_B)
#define SUB_B  (AMAT_B + BMAT_B)    // 15360 per 16-k sub-stage
#define STAGE_B (2 * SUB_B)         // 30720 per 32-k stage
#define NSTAGE  3
#define SMEM_B  (NSTAGE * STAGE_B)  // 92160
#define K32     (CDIM / 32)         // 24
#define NTILES  (KCODE / 256)       // 8

__global__ void __launch_bounds__(128, 2) vq_hmma_kernel() {
    extern __shared__ char smem[];
    const uint32_t sb = smem_u32(smem);

    const int tid   = threadIdx.x;
    const int lane  = tid & 31;
    const int warpN = tid >> 5;        // 0..3
    const int tg    = lane & 3;        // 0..3
    const int grp8  = lane >> 2;       // 0..7
    const int m0    = blockIdx.x * 64;

    // cp.async mapping: thread -> 5 x 16B chunks per 16-k sub
    const int ldRow  = tid >> 1;       // 0..63
    const int ldHalf = tid & 1;        // 0..1
    const uint32_t aOff = (uint32_t)(ldRow * LDAB + ldHalf * 16);
    const __half* AhiBase = g_Ahi + (size_t)(m0 + ldRow) * CDIM + ldHalf * 8;
    uint32_t bOff[4];
    size_t   bG[4];
#pragma unroll
    for (int r = 0; r < 4; r++) {
        bOff[r] = (uint32_t)((ldRow + r * 64) * LDAB + ldHalf * 16);
        bG[r]   = (size_t)(ldRow + r * 64) * CDIM + ldHalf * 8;
    }

    // ldmatrix addresses (within a sub-stage, relative)
    const uint32_t aRowOff =
        (uint32_t)((lane & 15) * LDAB + (lane >> 4) * 16);
    const uint32_t bRowOff =
        (uint32_t)((warpN * 64 + ((lane >> 4) << 3) + (lane & 7)) * LDAB +
                   ((lane >> 3) & 1) * 16);

    // per-thread best-2 per owned row-slot (4 mf x 2 halves = 8 slots)
    float b1[8], b2[8];
    int   i1[8], i2[8];
#pragma unroll
    for (int i = 0; i < 8; i++) {
        b1[i] = 3.4e38f; b2[i] = 3.4e38f; i1[i] = 0x7FFFFFFF; i2[i] = 0x7FFFFFFF;
    }

    // issue cursor over 32-k steps
    int in = 0, ik = 0;

    // prologue: issue data step 0 (both subs) into stage 0
    {
        const __half* bh0 = g_Bhi;
#pragma unroll
        for (int s = 0; s < 2; s++) {
            uint32_t ss = sb + (uint32_t)s * SUB_B;
            int gk = s * 16;
            cp16(ss + OFF_AH + aOff, AhiBase + gk);
#pragma unroll
            for (int r = 0; r < 4; r++)
                cp16(ss + OFF_BH + bOff[r], bh0 + bG[r] + gk);
        }
        CP_COMMIT();
        if (++ik == K32) { ik = 0; in++; }
    }

    for (int nt = 0; nt < NTILES; nt++) {
        const int n0 = nt * 256;

        float acc[4][8][4];
#pragma unroll
        for (int mf = 0; mf < 4; mf++)
#pragma unroll
            for (int nf = 0; nf < 8; nf++)
#pragma unroll
                for (int c = 0; c < 4; c++) acc[mf][nf][c] = 0.f;

        for (int ks = 0; ks < K32; ks++) {
            const int g = nt * K32 + ks;

            // issue data g+1 into stage (g+1)%3 BEFORE the wait.
            // stage (g+1)%3 was consumed at step g-2; all warps passed
            // barrier g-1 -> safe to refill pre-barrier.
            if (in < NTILES) {
                uint32_t st = sb + (uint32_t)((g + 1) % NSTAGE) * STAGE_B;
                const __half* bh0 = g_Bhi + (size_t)in * 256 * CDIM;
#pragma unroll
                for (int s = 0; s < 2; s++) {
                    uint32_t ss = st + (uint32_t)s * SUB_B;
                    int gk = ik * 32 + s * 16;
                    cp16(ss + OFF_AH + aOff, AhiBase + gk);
#pragma unroll
                    for (int r = 0; r < 4; r++)
                        cp16(ss + OFF_BH + bOff[r], bh0 + bG[r] + gk);
                }
                if (++ik == K32) { ik = 0; in++; }
            }
            CP_COMMIT();   // unconditional: keeps group counting exact at tail

            CP_WAIT1();    // newest outstanding = g+1 -> data g ready
            __syncthreads();

            const uint32_t stg = sb + (uint32_t)(g % NSTAGE) * STAGE_B;

            // two 16-k sub-steps, no barrier between
#pragma unroll
            for (int s = 0; s < 2; s++) {
                const uint32_t stage = stg + (uint32_t)s * SUB_B;

                uint32_t ah[4][4];
#pragma unroll
                for (int mf = 0; mf < 4; mf++) {
                    uint32_t a = stage + aRowOff + (uint32_t)(mf * 16 * LDAB);
                    ldsm_x4(ah[mf][0], ah[mf][1], ah[mf][2], ah[mf][3], a + OFF_AH);
                }

#pragma unroll
                for (int h = 0; h < 2; h++) {
                    uint32_t bh[4][2];
#pragma unroll
                    for (int p = 0; p < 2; p++) {
                        uint32_t b = stage + bRowOff +
                                     (uint32_t)((h * 32 + p * 16) * LDAB);
                        uint32_t r0, r1, r2, r3;
                        ldsm_x4(r0, r1, r2, r3, b + OFF_BH);
                        bh[p * 2][0] = r0; bh[p * 2][1] = r1;
                        bh[p * 2 + 1][0] = r2; bh[p * 2 + 1][1] = r3;
                    }
#pragma unroll
                    for (int mf = 0; mf < 4; mf++) {
#pragma unroll
                        for (int nf = 0; nf < 4; nf++) {
                            float* c = acc[mf][h * 4 + nf];
                            mma16816(c[0], c[1], c[2], c[3],
                                     ah[mf][0], ah[mf][1], ah[mf][2], ah[mf][3],
                                     bh[nf][0], bh[nf][1]);
                        }
                    }
                }
            }
        }

        // fold this n-tile into running best-2 (ascending n => first-occurrence)
#pragma unroll
        for (int nf = 0; nf < 8; nf++) {
            int n = n0 + warpN * 64 + nf * 8 + tg * 2;
            float cn0 = __ldg(&g_codeNorm[n]);
            float cn1 = __ldg(&g_codeNorm[n + 1]);
#pragma unroll
            for (int mf = 0; mf < 4; mf++) {
                float d0 = cn0 - 2.f * acc[mf][nf][0];
                float d1 = cn1 - 2.f * acc[mf][nf][1];
                float d2 = cn0 - 2.f * acc[mf][nf][2];
                float d3 = cn1 - 2.f * acc[mf][nf][3];
                int s0 = 2 * mf, s1 = 2 * mf + 1;
                if (d0 < b1[s0]) { b2[s0]=b1[s0]; i2[s0]=i1[s0]; b1[s0]=d0; i1[s0]=n; }
                else if (d0 < b2[s0]) { b2[s0]=d0; i2[s0]=n; }
                if (d1 < b1[s0]) { b2[s0]=b1[s0]; i2[s0]=i1[s0]; b1[s0]=d1; i1[s0]=n+1; }
                else if (d1 < b2[s0]) { b2[s0]=d1; i2[s0]=n+1; }
                if (d2 < b1[s1]) { b2[s1]=b1[s1]; i2[s1]=i1[s1]; b1[s1]=d2; i1[s1]=n; }
                else if (d2 < b2[s1]) { b2[s1]=d2; i2[s1]=n; }
                if (d3 < b1[s1]) { b2[s1]=b1[s1]; i2[s1]=i1[s1]; b1[s1]=d3; i1[s1]=n+1; }
                else if (d3 < b2[s1]) { b2[s1]=d3; i2[s1]=n+1; }
            }
        }
    }

    // drain remaining (empty) groups before reusing smem
    CP_WAIT0();
    __syncthreads();

    // per-row candidate pool: 16 owner threads x (best1, best2) = 32 entries
    float* sV = reinterpret_cast<float*>(smem);            // [64][32]
    int*   sI = reinterpret_cast<int*>(smem + 64 * 32 * 4);
    const int slot = warpN * 4 + tg;
#pragma unroll
    for (int mf = 0; mf < 4; mf++) {
        int r0 = mf * 16 + grp8;
        sV[r0 * 32 + slot]        = b1[2 * mf];
        sI[r0 * 32 + slot]        = i1[2 * mf];
        sV[r0 * 32 + slot + 16]   = b2[2 * mf];
        sI[r0 * 32 + slot + 16]   = i2[2 * mf];
        sV[(r0+8) * 32 + slot]      = b1[2 * mf + 1];
        sI[(r0+8) * 32 + slot]      = i1[2 * mf + 1];
        sV[(r0+8) * 32 + slot + 16] = b2[2 * mf + 1];
        sI[(r0+8) * 32 + slot + 16] = i2[2 * mf + 1];
    }
    __syncthreads();
    if (tid < 64) {
        float td[4] = {3.4e38f, 3.4e38f, 3.4e38f, 3.4e38f};
        int   ti[4] = {0x7FFFFFFF, 0x7FFFFFFF, 0x7FFFFFFF, 0x7FFFFFFF};
        for (int e = 0; e < 32; e++) {
            float v = sV[tid * 32 + e];
            int   id = sI[tid * 32 + e];
#pragma unroll
            for (int k = 0; k < 4; k++) {
                if (v < td[k] || (v == td[k] && id < ti[k])) {
                    for (int j = 3; j > k; j--) { td[j]=td[j-1]; ti[j]=ti[j-1]; }
                    td[k] = v; ti[k] = id;
                    break;
                }
            }
        }
#pragma unroll
        for (int c = 0; c < 4; c++) g_cand[(m0 + tid) * 4 + c] = ti[c];
    }
}

// ---------------------------------------------------------------------------
// Phase 2: exact fp32 re-rank of the 4 candidates per token. One warp/token.
// d = sum (x_i - e_i)^2 in fp32; min with idx tie-break -> g_idx.
// ---------------------------------------------------------------------------
__global__ void refine_kernel(const float* __restrict__ in,
                              const float* __restrict__ cb) {
    int w    = (blockIdx.x * blockDim.x + threadIdx.x) >> 5;
    int lane = threadIdx.x & 31;
    if (w >= MTOT) return;
    const float* xr = in + (size_t)w * CDIM;
    float x[24];
#pragma unroll
    for (int i = 0; i < 24; i++) x[i] = xr[lane + 32 * i];

    float bd = 3.4e38f;
    int   bi = 0x7FFFFFFF;
#pragma unroll
    for (int c = 0; c < 4; c++) {
        int idx = g_cand[w * 4 + c];
        const float* er = cb + (size_t)idx * CDIM;
        float s = 0.f;
#pragma unroll
        for (int i = 0; i < 24; i++) {
            float df = x[i] - er[lane + 32 * i];
            s = fmaf(df, df, s);
        }
#pragma unroll
        for (int o = 16; o; o >>= 1) s += __shfl_xor_sync(0xffffffffu, s, o);
        if (s < bd || (s == bd && idx < bi)) { bd = s; bi = idx; }
    }
    if (lane == 0) g_idx[w] = bi;
}

// ---------------------------------------------------------------------------
// att[t] = relu(dot(codebook[idx[t]], att_w[:,1])), + idx written as float
// ---------------------------------------------------------------------------
__global__ void att_kernel(const float* __restrict__ cb,
                           const float* __restrict__ att_w,
                           float* __restrict__ out_idx_f, int write_idx) {
    int gw   = (blockIdx.x * blockDim.x + threadIdx.x) >> 5;
    int lane = threadIdx.x & 31;
    if (gw >= MTOT) return;
    int idx = g_idx[gw];
    const float* row = cb + (size_t)idx * CDIM;
    float s = 0.f;
    for (int c = lane; c < CDIM; c += 32)
        s = fmaf(row[c], att_w[c * 3 + 1], s);
    for (int o = 16; o; o >>= 1) s += __shfl_down_sync(0xffffffffu, s, o);
    if (lane == 0) {
        g_att[gw] = fmaxf(s, 0.f);
        if (write_idx) out_idx_f[gw] = (float)idx;
    }
}

// ---------------------------------------------------------------------------
// softmax over L per batch -> g_mask
// ---------------------------------------------------------------------------
__global__ void softmax_kernel() {
    int b = blockIdx.x;
    int t = threadIdx.x;
    __shared__ float red[8];
    float v = (t < SEQL) ? g_att[b * SEQL + t] : -3.4e38f;

    float m = v;
    for (int o = 16; o; o >>= 1) m = fmaxf(m, __shfl_xor_sync(0xffffffffu, m, o));
    int lane = t & 31, wid = t >> 5;
    if (lane == 0) red[wid] = m;
    __syncthreads();
    if (wid == 0) {
        float x = (lane < 8) ? red[lane] : -3.4e38f;
        for (int o = 4; o; o >>= 1) x = fmaxf(x, __shfl_xor_sync(0xffffffffu, x, o));
        if (lane == 0) red[0] = x;
    }
    __syncthreads();
    float bmax = red[0];
    __syncthreads();

    float e = (t < SEQL) ? __expf(v - bmax) : 0.f;
    float s = e;
    for (int o = 16; o; o >>= 1) s += __shfl_xor_sync(0xffffffffu, s, o);
    if (lane == 0) red[wid] = s;
    __syncthreads();
    if (wid == 0) {
        float x = (lane < 8) ? red[lane] : 0.f;
        for (int o = 4; o; o >>= 1) x += __shfl_xor_sync(0xffffffffu, x, o);
        if (lane == 0) red[0] = x;
    }
    __syncthreads();
    float bsum = red[0];
    if (t < SEQL) g_mask[b * SEQL + t] = e / bsum;
}

// ---------------------------------------------------------------------------
// out[t,c] = codebook[idx[t]][c] + in[t,c] * mask[t]
// ---------------------------------------------------------------------------
__global__ void out_kernel(const float* __restrict__ in,
                           const float* __restrict__ cb,
                           float* __restrict__ out) {
    int t  = blockIdx.x;
    int c4 = threadIdx.x;          // 0..191
    float m = g_mask[t];
    int idx = g_idx[t];
    const float4* q4 = reinterpret_cast<const float4*>(cb + (size_t)idx * CDIM);
    const float4* x4 = reinterpret_cast<const float4*>(in + (size_t)t * CDIM);
    float4* o4 = reinterpret_cast<float4*>(out + (size_t)t * CDIM);
    float4 q = q4[c4];
    float4 x = x4[c4];
    o4[c4] = make_float4(fmaf(x.x, m, q.x), fmaf(x.y, m, q.y),
                         fmaf(x.z, m, q.z), fmaf(x.w, m, q.w));
}

// ---------------------------------------------------------------------------
extern "C" void kernel_launch(void* const* d_in, const int* in_sizes, int n_in,
                              void* d_out, int out_size) {
    const float* in_feas  = (const float*)d_in[0];   // [B, L, C]
    const float* codebook = (const float*)d_in[1];   // [K, C]
    const float* att_w    = (const float*)d_in[2];   // [1, C, 3]
    float* out = (float*)d_out;
    (void)in_sizes; (void)n_in;

    int write_idx = (out_size >= MTOT * CDIM + MTOT) ? 1 : 0;
    float* out_idx_f = out + (size_t)MTOT * CDIM;

    cudaFuncSetAttribute(vq_hmma_kernel,
                         cudaFuncAttributeMaxDynamicSharedMemorySize, SMEM_B);

    {
        int n4 = MTOT * CDIM / 4;   // 9,633,792
        convert_A_kernel<<<(n4 + 255) / 256, 256>>>(in_feas, n4);
    }
    {
        int n4 = KCODE * CDIM / 4;  // 393,216
        convert_B_kernel<<<(n4 + 255) / 256, 256>>>(codebook, n4);
    }
    codenorm_kernel<<<KCODE, 256>>>(codebook);

    vq_hmma_kernel<<<MTOT / 64, 128, SMEM_B>>>();
    refine_kernel<<<(MTOT * 32 + 255) / 256, 256>>>(in_feas, codebook);

    att_kernel<<<(MTOT * 32 + 255) / 256, 256>>>(codebook, att_w, out_idx_f, write_idx);
    softmax_kernel<<<BATCH, 256>>>();
    out_kernel<<<MTOT, CDIM / 4>>>(in_feas, codebook, out);
}

// round 14
// speedup vs baseline: 2.1591x; 1.0759x over previous
#include <cuda_runtime.h>
#include <cuda_fp16.h>
#include <cstdint>
#include <math.h>

#define BATCH 256
#define SEQL  196
#define CDIM  768
#define KCODE 2048
#define MTOT  (BATCH*SEQL)   // 50176

// ---------------------------------------------------------------------------
// scratch (no cudaMalloc allowed)
// ---------------------------------------------------------------------------
__device__ float  g_codeNorm[KCODE];
__device__ int    g_idx[MTOT];
__device__ int    g_cand[MTOT * 4];
__device__ float  g_att[MTOT];
__device__ float  g_mask[MTOT];
__device__ __half g_Ahi[(size_t)MTOT * CDIM];   // 77 MB
__device__ __half g_Bhi[(size_t)KCODE * CDIM];  // 3.1 MB

// ---------------------------------------------------------------------------
// helpers
// ---------------------------------------------------------------------------
__device__ __forceinline__ uint32_t smem_u32(const void* p) {
    uint32_t a;
    asm("{ .reg .u64 t; cvta.to.shared.u64 t, %1; cvt.u32.u64 %0, t; }"
        : "=r"(a) : "l"(p));
    return a;
}

__device__ __forceinline__ void cp16(uint32_t saddr, const void* gaddr) {
    asm volatile("cp.async.ca.shared.global [%0], [%1], 16;"
                 :: "r"(saddr), "l"(gaddr));
}
#define CP_COMMIT() asm volatile("cp.async.commit_group;" ::: "memory")
#define CP_WAIT2()  asm volatile("cp.async.wait_group 2;" ::: "memory")
#define CP_WAIT0()  asm volatile("cp.async.wait_group 0;" ::: "memory")

__device__ __forceinline__ void ldsm_x4(uint32_t& r0, uint32_t& r1,
                                        uint32_t& r2, uint32_t& r3,
                                        uint32_t addr) {
    asm volatile("ldmatrix.sync.aligned.m8n8.x4.shared.b16 {%0,%1,%2,%3}, [%4];"
                 : "=r"(r0), "=r"(r1), "=r"(r2), "=r"(r3) : "r"(addr));
}

__device__ __forceinline__ void mma16816(float& c0, float& c1, float& c2, float& c3,
                                         uint32_t a0, uint32_t a1, uint32_t a2, uint32_t a3,
                                         uint32_t b0, uint32_t b1) {
    asm volatile("mma.sync.aligned.m16n8k16.row.col.f32.f16.f16.f32 "
                 "{%0,%1,%2,%3}, {%4,%5,%6,%7}, {%8,%9}, {%0,%1,%2,%3};"
                 : "+f"(c0), "+f"(c1), "+f"(c2), "+f"(c3)
                 : "r"(a0), "r"(a1), "r"(a2), "r"(a3), "r"(b0), "r"(b1));
}

// ---------------------------------------------------------------------------
// convert: float -> fp16 hi only
// ---------------------------------------------------------------------------
__global__ void convert_A_kernel(const float* __restrict__ src, int n4) {
    int i = blockIdx.x * blockDim.x + threadIdx.x;
    if (i >= n4) return;
    float4 v = reinterpret_cast<const float4*>(src)[i];
    __half2* hp = reinterpret_cast<__half2*>(g_Ahi) + 2 * (size_t)i;
    hp[0] = __halves2half2(__float2half_rn(v.x), __float2half_rn(v.y));
    hp[1] = __halves2half2(__float2half_rn(v.z), __float2half_rn(v.w));
}

__global__ void convert_B_kernel(const float* __restrict__ src, int n4) {
    int i = blockIdx.x * blockDim.x + threadIdx.x;
    if (i >= n4) return;
    float4 v = reinterpret_cast<const float4*>(src)[i];
    __half2* hp = reinterpret_cast<__half2*>(g_Bhi) + 2 * (size_t)i;
    hp[0] = __halves2half2(__float2half_rn(v.x), __float2half_rn(v.y));
    hp[1] = __halves2half2(__float2half_rn(v.z), __float2half_rn(v.w));
}

// ---------------------------------------------------------------------------
// codebook row norms ||e||^2 (fp32 exact)
// ---------------------------------------------------------------------------
__global__ void codenorm_kernel(const float* __restrict__ cb) {
    int k = blockIdx.x;
    const float* row = cb + (size_t)k * CDIM;
    float s = 0.f;
    for (int c = threadIdx.x; c < CDIM; c += blockDim.x) {
        float v = row[c];
        s += v * v;
    }
    for (int o = 16; o; o >>= 1) s += __shfl_down_sync(0xffffffffu, s, o);
    __shared__ float red[8];
    int lane = threadIdx.x & 31, wid = threadIdx.x >> 5;
    if (lane == 0) red[wid] = s;
    __syncthreads();
    if (threadIdx.x == 0) {
        float t = 0.f;
        for (int w = 0; w < (int)(blockDim.x >> 5); w++) t += red[w];
        g_codeNorm[k] = t;
    }
}

// ---------------------------------------------------------------------------
// Phase 1: approximate distance GEMM (hi x hi) + top-4 candidate select.
// CTA 128(M) x 256(N), 8 warps (2M x 4N), warp tile 64x64, k-step 16.
// 4-stage cp.async pipeline, lookahead 2, issue-before-wait, one sync/step.
// (= R7's proven geometry, hi-only.) Each thread keeps best-2 per owned
// row-slot; per-row reduce picks top-4 of 32 into g_cand; phase 2 re-ranks
// exactly in fp32.
// ---------------------------------------------------------------------------
#define LDAB   48                   // bytes per SMEM row (16 halfs + 8 pad)
#define AMAT_B (128 * LDAB)         // 6144
#define BMAT_B (256 * LDAB)         // 12288
#define OFF_AH 0
#define OFF_BH (AMAT_B)
#define STAGE_B (AMAT_B + BMAT_B)   // 18432
#define NSTAGE  4
#define SMEM_B  (NSTAGE * STAGE_B)  // 73728
#define KSTEPS  (CDIM / 16)         // 48
#define NTILES  (KCODE / 256)       // 8
#define LOOKAHEAD 2

__global__ void __launch_bounds__(256, 1) vq_hmma_kernel() {
    extern __shared__ char smem[];
    const uint32_t sb = smem_u32(smem);

    const int tid   = threadIdx.x;
    const int lane  = tid & 31;
    const int warp  = tid >> 5;
    const int warpM = warp >> 2;       // 0..1
    const int warpN = warp & 3;        // 0..3
    const int tg    = lane & 3;        // 0..3
    const int grp8  = lane >> 2;       // 0..7
    const int m0    = blockIdx.x * 128;

    // cp.async mapping: thread -> 3 x 16B chunks (A row + 2 B rows)
    const int ldRow  = tid >> 1;       // 0..127
    const int ldHalf = tid & 1;        // 0..1
    const uint32_t aOff  = (uint32_t)(ldRow * LDAB + ldHalf * 16);
    const uint32_t bOff0 = aOff;
    const uint32_t bOff1 = (uint32_t)((ldRow + 128) * LDAB + ldHalf * 16);
    const __half* AhiBase = g_Ahi + (size_t)(m0 + ldRow) * CDIM + ldHalf * 8;
    const size_t  bG0 = (size_t)ldRow * CDIM + ldHalf * 8;
    const size_t  bG1 = (size_t)(ldRow + 128) * CDIM + ldHalf * 8;

    // ldmatrix addresses (within a stage, relative)
    const uint32_t aRowOff =
        (uint32_t)((warpM * 64 + (lane & 15)) * LDAB + (lane >> 4) * 16);
    const uint32_t bRowOff =
        (uint32_t)((warpN * 64 + ((lane >> 4) << 3) + (lane & 7)) * LDAB +
                   ((lane >> 3) & 1) * 16);

    // per-thread best-2 per owned row-slot (4 mf x 2 halves = 8 slots)
    float b1[8], b2[8];
    int   i1[8], i2[8];
#pragma unroll
    for (int i = 0; i < 8; i++) {
        b1[i] = 3.4e38f; b2[i] = 3.4e38f; i1[i] = 0x7FFFFFFF; i2[i] = 0x7FFFFFFF;
    }

    // issue cursor
    int in = 0, ik = 0;

    // prologue: issue data steps 0..LOOKAHEAD-1
#pragma unroll
    for (int p = 0; p < LOOKAHEAD; p++) {
        uint32_t st = sb + (uint32_t)p * STAGE_B;
        int gk = ik * 16;
        const __half* bh0 = g_Bhi + (size_t)in * 256 * CDIM;
        cp16(st + OFF_AH + aOff, AhiBase + gk);
        cp16(st + OFF_BH + bOff0, bh0 + bG0 + gk);
        cp16(st + OFF_BH + bOff1, bh0 + bG1 + gk);
        CP_COMMIT();
        if (++ik == KSTEPS) { ik = 0; in++; }
    }

    for (int nt = 0; nt < NTILES; nt++) {
        const int n0 = nt * 256;

        float acc[4][8][4];
#pragma unroll
        for (int mf = 0; mf < 4; mf++)
#pragma unroll
            for (int nf = 0; nf < 8; nf++)
#pragma unroll
                for (int c = 0; c < 4; c++) acc[mf][nf][c] = 0.f;

        for (int ks = 0; ks < KSTEPS; ks++) {
            const int g = nt * KSTEPS + ks;

            // issue data g+2 into stage (g+2)%4 BEFORE the wait.
            // stage consumed at g-2; all warps passed barrier g-1 -> safe.
            if (in < NTILES) {
                uint32_t st = sb +
                    (uint32_t)((g + LOOKAHEAD) & (NSTAGE - 1)) * STAGE_B;
                int gk = ik * 16;
                const __half* bh0 = g_Bhi + (size_t)in * 256 * CDIM;
                cp16(st + OFF_AH + aOff, AhiBase + gk);
                cp16(st + OFF_BH + bOff0, bh0 + bG0 + gk);
                cp16(st + OFF_BH + bOff1, bh0 + bG1 + gk);
                if (++ik == KSTEPS) { ik = 0; in++; }
            }
            CP_COMMIT();   // unconditional: keeps group counting exact at tail

            CP_WAIT2();
            __syncthreads();

            const uint32_t stage = sb + (uint32_t)(g & (NSTAGE - 1)) * STAGE_B;

            uint32_t ah[4][4];
#pragma unroll
            for (int mf = 0; mf < 4; mf++) {
                uint32_t a = stage + aRowOff + (uint32_t)(mf * 16 * LDAB);
                ldsm_x4(ah[mf][0], ah[mf][1], ah[mf][2], ah[mf][3], a + OFF_AH);
            }

#pragma unroll
            for (int h = 0; h < 2; h++) {
                uint32_t bh[4][2];
#pragma unroll
                for (int p = 0; p < 2; p++) {
                    uint32_t b = stage + bRowOff +
                                 (uint32_t)((h * 32 + p * 16) * LDAB);
                    uint32_t r0, r1, r2, r3;
                    ldsm_x4(r0, r1, r2, r3, b + OFF_BH);
                    bh[p * 2][0] = r0; bh[p * 2][1] = r1;
                    bh[p * 2 + 1][0] = r2; bh[p * 2 + 1][1] = r3;
                }
#pragma unroll
                for (int mf = 0; mf < 4; mf++) {
#pragma unroll
                    for (int nf = 0; nf < 4; nf++) {
                        float* c = acc[mf][h * 4 + nf];
                        mma16816(c[0], c[1], c[2], c[3],
                                 ah[mf][0], ah[mf][1], ah[mf][2], ah[mf][3],
                                 bh[nf][0], bh[nf][1]);
                    }
                }
            }
        }

        // fold this n-tile into running best-2 (ascending n => first-occurrence)
#pragma unroll
        for (int nf = 0; nf < 8; nf++) {
            int n = n0 + warpN * 64 + nf * 8 + tg * 2;
            float cn0 = __ldg(&g_codeNorm[n]);
            float cn1 = __ldg(&g_codeNorm[n + 1]);
#pragma unroll
            for (int mf = 0; mf < 4; mf++) {
                float d0 = cn0 - 2.f * acc[mf][nf][0];
                float d1 = cn1 - 2.f * acc[mf][nf][1];
                float d2 = cn0 - 2.f * acc[mf][nf][2];
                float d3 = cn1 - 2.f * acc[mf][nf][3];
                int s0 = 2 * mf, s1 = 2 * mf + 1;
                if (d0 < b1[s0]) { b2[s0]=b1[s0]; i2[s0]=i1[s0]; b1[s0]=d0; i1[s0]=n; }
                else if (d0 < b2[s0]) { b2[s0]=d0; i2[s0]=n; }
                if (d1 < b1[s0]) { b2[s0]=b1[s0]; i2[s0]=i1[s0]; b1[s0]=d1; i1[s0]=n+1; }
                else if (d1 < b2[s0]) { b2[s0]=d1; i2[s0]=n+1; }
                if (d2 < b1[s1]) { b2[s1]=b1[s1]; i2[s1]=i1[s1]; b1[s1]=d2; i1[s1]=n; }
                else if (d2 < b2[s1]) { b2[s1]=d2; i2[s1]=n; }
                if (d3 < b1[s1]) { b2[s1]=b1[s1]; i2[s1]=i1[s1]; b1[s1]=d3; i1[s1]=n+1; }
                else if (d3 < b2[s1]) { b2[s1]=d3; i2[s1]=n+1; }
            }
        }
    }

    // drain remaining (empty) groups before reusing smem
    CP_WAIT0();
    __syncthreads();

    // per-row candidate pool: 16 owner threads x (best1, best2) = 32 entries
    float* sV = reinterpret_cast<float*>(smem);            // [128][32]
    int*   sI = reinterpret_cast<int*>(smem + 128 * 32 * 4);
    const int slot = warpN * 4 + tg;
#pragma unroll
    for (int mf = 0; mf < 4; mf++) {
        int r0 = warpM * 64 + mf * 16 + grp8;
        sV[r0 * 32 + slot]        = b1[2 * mf];
        sI[r0 * 32 + slot]        = i1[2 * mf];
        sV[r0 * 32 + slot + 16]   = b2[2 * mf];
        sI[r0 * 32 + slot + 16]   = i2[2 * mf];
        sV[(r0+8) * 32 + slot]      = b1[2 * mf + 1];
        sI[(r0+8) * 32 + slot]      = i1[2 * mf + 1];
        sV[(r0+8) * 32 + slot + 16] = b2[2 * mf + 1];
        sI[(r0+8) * 32 + slot + 16] = i2[2 * mf + 1];
    }
    __syncthreads();
    if (tid < 128) {
        float td[4] = {3.4e38f, 3.4e38f, 3.4e38f, 3.4e38f};
        int   ti[4] = {0x7FFFFFFF, 0x7FFFFFFF, 0x7FFFFFFF, 0x7FFFFFFF};
        for (int e = 0; e < 32; e++) {
            float v = sV[tid * 32 + e];
            int   id = sI[tid * 32 + e];
#pragma unroll
            for (int k = 0; k < 4; k++) {
                if (v < td[k] || (v == td[k] && id < ti[k])) {
                    for (int j = 3; j > k; j--) { td[j]=td[j-1]; ti[j]=ti[j-1]; }
                    td[k] = v; ti[k] = id;
                    break;
                }
            }
        }
#pragma unroll
        for (int c = 0; c < 4; c++) g_cand[(m0 + tid) * 4 + c] = ti[c];
    }
}

// ---------------------------------------------------------------------------
// Phase 2: exact fp32 re-rank of the 4 candidates per token. One warp/token.
// ---------------------------------------------------------------------------
__global__ void refine_kernel(const float* __restrict__ in,
                              const float* __restrict__ cb) {
    int w    = (blockIdx.x * blockDim.x + threadIdx.x) >> 5;
    int lane = threadIdx.x & 31;
    if (w >= MTOT) return;
    const float* xr = in + (size_t)w * CDIM;
    float x[24];
#pragma unroll
    for (int i = 0; i < 24; i++) x[i] = xr[lane + 32 * i];

    float bd = 3.4e38f;
    int   bi = 0x7FFFFFFF;
#pragma unroll
    for (int c = 0; c < 4; c++) {
        int idx = g_cand[w * 4 + c];
        const float* er = cb + (size_t)idx * CDIM;
        float s = 0.f;
#pragma unroll
        for (int i = 0; i < 24; i++) {
            float df = x[i] - er[lane + 32 * i];
            s = fmaf(df, df, s);
        }
#pragma unroll
        for (int o = 16; o; o >>= 1) s += __shfl_xor_sync(0xffffffffu, s, o);
        if (s < bd || (s == bd && idx < bi)) { bd = s; bi = idx; }
    }
    if (lane == 0) g_idx[w] = bi;
}

// ---------------------------------------------------------------------------
// att[t] = relu(dot(codebook[idx[t]], att_w[:,1])), + idx written as float
// ---------------------------------------------------------------------------
__global__ void att_kernel(const float* __restrict__ cb,
                           const float* __restrict__ att_w,
                           float* __restrict__ out_idx_f, int write_idx) {
    int gw   = (blockIdx.x * blockDim.x + threadIdx.x) >> 5;
    int lane = threadIdx.x & 31;
    if (gw >= MTOT) return;
    int idx = g_idx[gw];
    const float* row = cb + (size_t)idx * CDIM;
    float s = 0.f;
    for (int c = lane; c < CDIM; c += 32)
        s = fmaf(row[c], att_w[c * 3 + 1], s);
    for (int o = 16; o; o >>= 1) s += __shfl_down_sync(0xffffffffu, s, o);
    if (lane == 0) {
        g_att[gw] = fmaxf(s, 0.f);
        if (write_idx) out_idx_f[gw] = (float)idx;
    }
}

// ---------------------------------------------------------------------------
// softmax over L per batch -> g_mask
// ---------------------------------------------------------------------------
__global__ void softmax_kernel() {
    int b = blockIdx.x;
    int t = threadIdx.x;
    __shared__ float red[8];
    float v = (t < SEQL) ? g_att[b * SEQL + t] : -3.4e38f;

    float m = v;
    for (int o = 16; o; o >>= 1) m = fmaxf(m, __shfl_xor_sync(0xffffffffu, m, o));
    int lane = t & 31, wid = t >> 5;
    if (lane == 0) red[wid] = m;
    __syncthreads();
    if (wid == 0) {
        float x = (lane < 8) ? red[lane] : -3.4e38f;
        for (int o = 4; o; o >>= 1) x = fmaxf(x, __shfl_xor_sync(0xffffffffu, x, o));
        if (lane == 0) red[0] = x;
    }
    __syncthreads();
    float bmax = red[0];
    __syncthreads();

    float e = (t < SEQL) ? __expf(v - bmax) : 0.f;
    float s = e;
    for (int o = 16; o; o >>= 1) s += __shfl_xor_sync(0xffffffffu, s, o);
    if (lane == 0) red[wid] = s;
    __syncthreads();
    if (wid == 0) {
        float x = (lane < 8) ? red[lane] : 0.f;
        for (int o = 4; o; o >>= 1) x += __shfl_xor_sync(0xffffffffu, x, o);
        if (lane == 0) red[0] = x;
    }
    __syncthreads();
    float bsum = red[0];
    if (t < SEQL) g_mask[b * SEQL + t] = e / bsum;
}

// ---------------------------------------------------------------------------
// out[t,c] = codebook[idx[t]][c] + in[t,c] * mask[t]
// ---------------------------------------------------------------------------
__global__ void out_kernel(const float* __restrict__ in,
                           const float* __restrict__ cb,
                           float* __restrict__ out) {
    int t  = blockIdx.x;
    int c4 = threadIdx.x;          // 0..191
    float m = g_mask[t];
    int idx = g_idx[t];
    const float4* q4 = reinterpret_cast<const float4*>(cb + (size_t)idx * CDIM);
    const float4* x4 = reinterpret_cast<const float4*>(in + (size_t)t * CDIM);
    float4* o4 = reinterpret_cast<float4*>(out + (size_t)t * CDIM);
    float4 q = q4[c4];
    float4 x = x4[c4];
    o4[c4] = make_float4(fmaf(x.x, m, q.x), fmaf(x.y, m, q.y),
                         fmaf(x.z, m, q.z), fmaf(x.w, m, q.w));
}

// ---------------------------------------------------------------------------
extern "C" void kernel_launch(void* const* d_in, const int* in_sizes, int n_in,
                              void* d_out, int out_size) {
    const float* in_feas  = (const float*)d_in[0];   // [B, L, C]
    const float* codebook = (const float*)d_in[1];   // [K, C]
    const float* att_w    = (const float*)d_in[2];   // [1, C, 3]
    float* out = (float*)d_out;
    (void)in_sizes; (void)n_in;

    int write_idx = (out_size >= MTOT * CDIM + MTOT) ? 1 : 0;
    float* out_idx_f = out + (size_t)MTOT * CDIM;

    cudaFuncSetAttribute(vq_hmma_kernel,
                         cudaFuncAttributeMaxDynamicSharedMemorySize, SMEM_B);

    {
        int n4 = MTOT * CDIM / 4;   // 9,633,792
        convert_A_kernel<<<(n4 + 255) / 256, 256>>>(in_feas, n4);
    }
    {
        int n4 = KCODE * CDIM / 4;  // 393,216
        convert_B_kernel<<<(n4 + 255) / 256, 256>>>(codebook, n4);
    }
    codenorm_kernel<<<KCODE, 256>>>(codebook);

    vq_hmma_kernel<<<MTOT / 128, 256, SMEM_B>>>();
    refine_kernel<<<(MTOT * 32 + 255) / 256, 256>>>(in_feas, codebook);

    att_kernel<<<(MTOT * 32 + 255) / 256, 256>>>(codebook, att_w, out_idx_f, write_idx);
    softmax_kernel<<<BATCH, 256>>>();
    out_kernel<<<MTOT, CDIM / 4>>>(in_feas, codebook, out);
}

// round 16
// speedup vs baseline: 2.2667x; 1.0498x over previous
#include <cuda_runtime.h>
#include <cuda_fp16.h>
#include <cstdint>
#include <math.h>

#define BATCH 256
#define SEQL  196
#define CDIM  768
#define KCODE 2048
#define MTOT  (BATCH*SEQL)   // 50176

// ---------------------------------------------------------------------------
// scratch (no cudaMalloc allowed)
// ---------------------------------------------------------------------------
__device__ float  g_codeNorm[KCODE];
__device__ int    g_idx[MTOT];
__device__ int    g_cand[MTOT * 4];
__device__ float  g_att[MTOT];
__device__ float  g_mask[MTOT];
__device__ __half g_Ahi[(size_t)MTOT * CDIM];   // 77 MB
__device__ __half g_Bhi[(size_t)KCODE * CDIM];  // 3.1 MB

// ---------------------------------------------------------------------------
// helpers
// ---------------------------------------------------------------------------
__device__ __forceinline__ uint32_t smem_u32(const void* p) {
    uint32_t a;
    asm("{ .reg .u64 t; cvta.to.shared.u64 t, %1; cvt.u32.u64 %0, t; }"
        : "=r"(a) : "l"(p));
    return a;
}

__device__ __forceinline__ void cp16(uint32_t saddr, const void* gaddr) {
    asm volatile("cp.async.ca.shared.global [%0], [%1], 16;"
                 :: "r"(saddr), "l"(gaddr));
}
#define CP_COMMIT() asm volatile("cp.async.commit_group;" ::: "memory")
#define CP_WAIT1()  asm volatile("cp.async.wait_group 1;" ::: "memory")
#define CP_WAIT0()  asm volatile("cp.async.wait_group 0;" ::: "memory")

__device__ __forceinline__ void ldsm_x4(uint32_t& r0, uint32_t& r1,
                                        uint32_t& r2, uint32_t& r3,
                                        uint32_t addr) {
    asm volatile("ldmatrix.sync.aligned.m8n8.x4.shared.b16 {%0,%1,%2,%3}, [%4];"
                 : "=r"(r0), "=r"(r1), "=r"(r2), "=r"(r3) : "r"(addr));
}

__device__ __forceinline__ void mma16816(float& c0, float& c1, float& c2, float& c3,
                                         uint32_t a0, uint32_t a1, uint32_t a2, uint32_t a3,
                                         uint32_t b0, uint32_t b1) {
    asm volatile("mma.sync.aligned.m16n8k16.row.col.f32.f16.f16.f32 "
                 "{%0,%1,%2,%3}, {%4,%5,%6,%7}, {%8,%9}, {%0,%1,%2,%3};"
                 : "+f"(c0), "+f"(c1), "+f"(c2), "+f"(c3)
                 : "r"(a0), "r"(a1), "r"(a2), "r"(a3), "r"(b0), "r"(b1));
}

// ---------------------------------------------------------------------------
// convert: float -> fp16 hi only
// ---------------------------------------------------------------------------
__global__ void convert_A_kernel(const float* __restrict__ src, int n4) {
    int i = blockIdx.x * blockDim.x + threadIdx.x;
    if (i >= n4) return;
    float4 v = reinterpret_cast<const float4*>(src)[i];
    __half2* hp = reinterpret_cast<__half2*>(g_Ahi) + 2 * (size_t)i;
    hp[0] = __halves2half2(__float2half_rn(v.x), __float2half_rn(v.y));
    hp[1] = __halves2half2(__float2half_rn(v.z), __float2half_rn(v.w));
}

__global__ void convert_B_kernel(const float* __restrict__ src, int n4) {
    int i = blockIdx.x * blockDim.x + threadIdx.x;
    if (i >= n4) return;
    float4 v = reinterpret_cast<const float4*>(src)[i];
    __half2* hp = reinterpret_cast<__half2*>(g_Bhi) + 2 * (size_t)i;
    hp[0] = __halves2half2(__float2half_rn(v.x), __float2half_rn(v.y));
    hp[1] = __halves2half2(__float2half_rn(v.z), __float2half_rn(v.w));
}

// ---------------------------------------------------------------------------
// codebook row norms ||e||^2 (fp32 exact)
// ---------------------------------------------------------------------------
__global__ void codenorm_kernel(const float* __restrict__ cb) {
    int k = blockIdx.x;
    const float* row = cb + (size_t)k * CDIM;
    float s = 0.f;
    for (int c = threadIdx.x; c < CDIM; c += blockDim.x) {
        float v = row[c];
        s += v * v;
    }
    for (int o = 16; o; o >>= 1) s += __shfl_down_sync(0xffffffffu, s, o);
    __shared__ float red[8];
    int lane = threadIdx.x & 31, wid = threadIdx.x >> 5;
    if (lane == 0) red[wid] = s;
    __syncthreads();
    if (threadIdx.x == 0) {
        float t = 0.f;
        for (int w = 0; w < (int)(blockDim.x >> 5); w++) t += red[w];
        g_codeNorm[k] = t;
    }
}

// ---------------------------------------------------------------------------
// Phase 1: approximate distance GEMM (hi x hi) + top-4 candidate select.
// CTA 128(M) x 256(N), 8 warps (2M x 4N), warp tile 64x64.
// k-step 32 = two 16-k sub-steps per barrier -> 192 barriers total.
// 3-stage cp.async pipeline, lookahead 1, issue-before-wait, one sync/step.
// Each thread keeps best-2 per owned row-slot; per-row reduce picks top-4
// of 32 into g_cand; phase 2 re-ranks exactly in fp32.
// ---------------------------------------------------------------------------
#define LDAB   48                   // bytes per SMEM row (16 halfs + 8 pad)
#define AMAT_B (128 * LDAB)         // 6144
#define BMAT_B (256 * LDAB)         // 12288
#define OFF_AH 0
#define OFF_BH (AMAT_B)
#define SUB_B  (AMAT_B + BMAT_B)    // 18432 per 16-k sub-stage
#define STAGE_B (2 * SUB_B)         // 36864 per 32-k stage
#define NSTAGE  3
#define SMEM_B  (NSTAGE * STAGE_B)  // 110592
#define K32     (CDIM / 32)         // 24
#define NTILES  (KCODE / 256)       // 8

__global__ void __launch_bounds__(256, 1) vq_hmma_kernel() {
    extern __shared__ char smem[];
    const uint32_t sb = smem_u32(smem);

    const int tid   = threadIdx.x;
    const int lane  = tid & 31;
    const int warp  = tid >> 5;
    const int warpM = warp >> 2;       // 0..1
    const int warpN = warp & 3;        // 0..3
    const int tg    = lane & 3;        // 0..3
    const int grp8  = lane >> 2;       // 0..7
    const int m0    = blockIdx.x * 128;

    // cp.async mapping: thread -> 3 x 16B chunks per 16-k sub (A + 2 B rows)
    const int ldRow  = tid >> 1;       // 0..127
    const int ldHalf = tid & 1;        // 0..1
    const uint32_t aOff  = (uint32_t)(ldRow * LDAB + ldHalf * 16);
    const uint32_t bOff0 = aOff;
    const uint32_t bOff1 = (uint32_t)((ldRow + 128) * LDAB + ldHalf * 16);
    const __half* AhiBase = g_Ahi + (size_t)(m0 + ldRow) * CDIM + ldHalf * 8;
    const size_t  bG0 = (size_t)ldRow * CDIM + ldHalf * 8;
    const size_t  bG1 = (size_t)(ldRow + 128) * CDIM + ldHalf * 8;

    // ldmatrix addresses (within a sub-stage, relative)
    const uint32_t aRowOff =
        (uint32_t)((warpM * 64 + (lane & 15)) * LDAB + (lane >> 4) * 16);
    const uint32_t bRowOff =
        (uint32_t)((warpN * 64 + ((lane >> 4) << 3) + (lane & 7)) * LDAB +
                   ((lane >> 3) & 1) * 16);

    // per-thread best-2 per owned row-slot (4 mf x 2 halves = 8 slots)
    float b1[8], b2[8];
    int   i1[8], i2[8];
#pragma unroll
    for (int i = 0; i < 8; i++) {
        b1[i] = 3.4e38f; b2[i] = 3.4e38f; i1[i] = 0x7FFFFFFF; i2[i] = 0x7FFFFFFF;
    }

    // issue cursor over 32-k steps
    int in = 0, ik = 0;

    // prologue: issue data step 0 (both subs) into stage 0
    {
        const __half* bh0 = g_Bhi;
#pragma unroll
        for (int s = 0; s < 2; s++) {
            uint32_t ss = sb + (uint32_t)s * SUB_B;
            int gk = s * 16;
            cp16(ss + OFF_AH + aOff, AhiBase + gk);
            cp16(ss + OFF_BH + bOff0, bh0 + bG0 + gk);
            cp16(ss + OFF_BH + bOff1, bh0 + bG1 + gk);
        }
        CP_COMMIT();
        if (++ik == K32) { ik = 0; in++; }
    }

    for (int nt = 0; nt < NTILES; nt++) {
        const int n0 = nt * 256;

        float acc[4][8][4];
#pragma unroll
        for (int mf = 0; mf < 4; mf++)
#pragma unroll
            for (int nf = 0; nf < 8; nf++)
#pragma unroll
                for (int c = 0; c < 4; c++) acc[mf][nf][c] = 0.f;

        for (int ks = 0; ks < K32; ks++) {
            const int g = nt * K32 + ks;

            // issue data g+1 into stage (g+1)%3 BEFORE the wait.
            // stage (g+1)%3 was consumed at step g-2; all warps passed
            // barrier g-1 -> safe to refill pre-barrier.
            if (in < NTILES) {
                uint32_t st = sb + (uint32_t)((g + 1) % NSTAGE) * STAGE_B;
                const __half* bh0 = g_Bhi + (size_t)in * 256 * CDIM;
#pragma unroll
                for (int s = 0; s < 2; s++) {
                    uint32_t ss = st + (uint32_t)s * SUB_B;
                    int gk = ik * 32 + s * 16;
                    cp16(ss + OFF_AH + aOff, AhiBase + gk);
                    cp16(ss + OFF_BH + bOff0, bh0 + bG0 + gk);
                    cp16(ss + OFF_BH + bOff1, bh0 + bG1 + gk);
                }
                if (++ik == K32) { ik = 0; in++; }
            }
            CP_COMMIT();   // unconditional: keeps group counting exact at tail

            CP_WAIT1();    // newest outstanding = g+1 -> data g ready
            __syncthreads();

            const uint32_t stg = sb + (uint32_t)(g % NSTAGE) * STAGE_B;

            // two 16-k sub-steps, no barrier between (independent LDSM chains)
#pragma unroll
            for (int s = 0; s < 2; s++) {
                const uint32_t stage = stg + (uint32_t)s * SUB_B;

                uint32_t ah[4][4];
#pragma unroll
                for (int mf = 0; mf < 4; mf++) {
                    uint32_t a = stage + aRowOff + (uint32_t)(mf * 16 * LDAB);
                    ldsm_x4(ah[mf][0], ah[mf][1], ah[mf][2], ah[mf][3], a + OFF_AH);
                }

#pragma unroll
                for (int h = 0; h < 2; h++) {
                    uint32_t bh[4][2];
#pragma unroll
                    for (int p = 0; p < 2; p++) {
                        uint32_t b = stage + bRowOff +
                                     (uint32_t)((h * 32 + p * 16) * LDAB);
                        uint32_t r0, r1, r2, r3;
                        ldsm_x4(r0, r1, r2, r3, b + OFF_BH);
                        bh[p * 2][0] = r0; bh[p * 2][1] = r1;
                        bh[p * 2 + 1][0] = r2; bh[p * 2 + 1][1] = r3;
                    }
#pragma unroll
                    for (int mf = 0; mf < 4; mf++) {
#pragma unroll
                        for (int nf = 0; nf < 4; nf++) {
                            float* c = acc[mf][h * 4 + nf];
                            mma16816(c[0], c[1], c[2], c[3],
                                     ah[mf][0], ah[mf][1], ah[mf][2], ah[mf][3],
                                     bh[nf][0], bh[nf][1]);
                        }
                    }
                }
            }
        }

        // fold this n-tile into running best-2 (ascending n => first-occurrence)
#pragma unroll
        for (int nf = 0; nf < 8; nf++) {
            int n = n0 + warpN * 64 + nf * 8 + tg * 2;
            float cn0 = __ldg(&g_codeNorm[n]);
            float cn1 = __ldg(&g_codeNorm[n + 1]);
#pragma unroll
            for (int mf = 0; mf < 4; mf++) {
                float d0 = cn0 - 2.f * acc[mf][nf][0];
                float d1 = cn1 - 2.f * acc[mf][nf][1];
                float d2 = cn0 - 2.f * acc[mf][nf][2];
                float d3 = cn1 - 2.f * acc[mf][nf][3];
                int s0 = 2 * mf, s1 = 2 * mf + 1;
                if (d0 < b1[s0]) { b2[s0]=b1[s0]; i2[s0]=i1[s0]; b1[s0]=d0; i1[s0]=n; }
                else if (d0 < b2[s0]) { b2[s0]=d0; i2[s0]=n; }
                if (d1 < b1[s0]) { b2[s0]=b1[s0]; i2[s0]=i1[s0]; b1[s0]=d1; i1[s0]=n+1; }
                else if (d1 < b2[s0]) { b2[s0]=d1; i2[s0]=n+1; }
                if (d2 < b1[s1]) { b2[s1]=b1[s1]; i2[s1]=i1[s1]; b1[s1]=d2; i1[s1]=n; }
                else if (d2 < b2[s1]) { b2[s1]=d2; i2[s1]=n; }
                if (d3 < b1[s1]) { b2[s1]=b1[s1]; i2[s1]=i1[s1]; b1[s1]=d3; i1[s1]=n+1; }
                else if (d3 < b2[s1]) { b2[s1]=d3; i2[s1]=n+1; }
            }
        }
    }

    // drain remaining (empty) groups before reusing smem
    CP_WAIT0();
    __syncthreads();

    // per-row candidate pool: 16 owner threads x (best1, best2) = 32 entries
    float* sV = reinterpret_cast<float*>(smem);            // [128][32]
    int*   sI = reinterpret_cast<int*>(smem + 128 * 32 * 4);
    const int slot = warpN * 4 + tg;
#pragma unroll
    for (int mf = 0; mf < 4; mf++) {
        int r0 = warpM * 64 + mf * 16 + grp8;
        sV[r0 * 32 + slot]        = b1[2 * mf];
        sI[r0 * 32 + slot]        = i1[2 * mf];
        sV[r0 * 32 + slot + 16]   = b2[2 * mf];
        sI[r0 * 32 + slot + 16]   = i2[2 * mf];
        sV[(r0+8) * 32 + slot]      = b1[2 * mf + 1];
        sI[(r0+8) * 32 + slot]      = i1[2 * mf + 1];
        sV[(r0+8) * 32 + slot + 16] = b2[2 * mf + 1];
        sI[(r0+8) * 32 + slot + 16] = i2[2 * mf + 1];
    }
    __syncthreads();
    if (tid < 128) {
        float td[4] = {3.4e38f, 3.4e38f, 3.4e38f, 3.4e38f};
        int   ti[4] = {0x7FFFFFFF, 0x7FFFFFFF, 0x7FFFFFFF, 0x7FFFFFFF};
        for (int e = 0; e < 32; e++) {
            float v = sV[tid * 32 + e];
            int   id = sI[tid * 32 + e];
#pragma unroll
            for (int k = 0; k < 4; k++) {
                if (v < td[k] || (v == td[k] && id < ti[k])) {
                    for (int j = 3; j > k; j--) { td[j]=td[j-1]; ti[j]=ti[j-1]; }
                    td[k] = v; ti[k] = id;
                    break;
                }
            }
        }
#pragma unroll
        for (int c = 0; c < 4; c++) g_cand[(m0 + tid) * 4 + c] = ti[c];
    }
}

// ---------------------------------------------------------------------------
// Phase 2: exact fp32 re-rank of the 4 candidates per token. One warp/token.
// ---------------------------------------------------------------------------
__global__ void refine_kernel(const float* __restrict__ in,
                              const float* __restrict__ cb) {
    int w    = (blockIdx.x * blockDim.x + threadIdx.x) >> 5;
    int lane = threadIdx.x & 31;
    if (w >= MTOT) return;
    const float* xr = in + (size_t)w * CDIM;
    float x[24];
#pragma unroll
    for (int i = 0; i < 24; i++) x[i] = xr[lane + 32 * i];

    float bd = 3.4e38f;
    int   bi = 0x7FFFFFFF;
#pragma unroll
    for (int c = 0; c < 4; c++) {
        int idx = g_cand[w * 4 + c];
        const float* er = cb + (size_t)idx * CDIM;
        float s = 0.f;
#pragma unroll
        for (int i = 0; i < 24; i++) {
            float df = x[i] - er[lane + 32 * i];
            s = fmaf(df, df, s);
        }
#pragma unroll
        for (int o = 16; o; o >>= 1) s += __shfl_xor_sync(0xffffffffu, s, o);
        if (s < bd || (s == bd && idx < bi)) { bd = s; bi = idx; }
    }
    if (lane == 0) g_idx[w] = bi;
}

// ---------------------------------------------------------------------------
// att[t] = relu(dot(codebook[idx[t]], att_w[:,1])), + idx written as float
// ---------------------------------------------------------------------------
__global__ void att_kernel(const float* __restrict__ cb,
                           const float* __restrict__ att_w,
                           float* __restrict__ out_idx_f, int write_idx) {
    int gw   = (blockIdx.x * blockDim.x + threadIdx.x) >> 5;
    int lane = threadIdx.x & 31;
    if (gw >= MTOT) return;
    int idx = g_idx[gw];
    const float* row = cb + (size_t)idx * CDIM;
    float s = 0.f;
    for (int c = lane; c < CDIM; c += 32)
        s = fmaf(row[c], att_w[c * 3 + 1], s);
    for (int o = 16; o; o >>= 1) s += __shfl_down_sync(0xffffffffu, s, o);
    if (lane == 0) {
        g_att[gw] = fmaxf(s, 0.f);
        if (write_idx) out_idx_f[gw] = (float)idx;
    }
}

// ---------------------------------------------------------------------------
// softmax over L per batch -> g_mask
// ---------------------------------------------------------------------------
__global__ void softmax_kernel() {
    int b = blockIdx.x;
    int t = threadIdx.x;
    __shared__ float red[8];
    float v = (t < SEQL) ? g_att[b * SEQL + t] : -3.4e38f;

    float m = v;
    for (int o = 16; o; o >>= 1) m = fmaxf(m, __shfl_xor_sync(0xffffffffu, m, o));
    int lane = t & 31, wid = t >> 5;
    if (lane == 0) red[wid] = m;
    __syncthreads();
    if (wid == 0) {
        float x = (lane < 8) ? red[lane] : -3.4e38f;
        for (int o = 4; o; o >>= 1) x = fmaxf(x, __shfl_xor_sync(0xffffffffu, x, o));
        if (lane == 0) red[0] = x;
    }
    __syncthreads();
    float bmax = red[0];
    __syncthreads();

    float e = (t < SEQL) ? __expf(v - bmax) : 0.f;
    float s = e;
    for (int o = 16; o; o >>= 1) s += __shfl_xor_sync(0xffffffffu, s, o);
    if (lane == 0) red[wid] = s;
    __syncthreads();
    if (wid == 0) {
        float x = (lane < 8) ? red[lane] : 0.f;
        for (int o = 4; o; o >>= 1) x += __shfl_xor_sync(0xffffffffu, x, o);
        if (lane == 0) red[0] = x;
    }
    __syncthreads();
    float bsum = red[0];
    if (t < SEQL) g_mask[b * SEQL + t] = e / bsum;
}

// ---------------------------------------------------------------------------
// out[t,c] = codebook[idx[t]][c] + in[t,c] * mask[t]
// ---------------------------------------------------------------------------
__global__ void out_kernel(const float* __restrict__ in,
                           const float* __restrict__ cb,
                           float* __restrict__ out) {
    int t  = blockIdx.x;
    int c4 = threadIdx.x;          // 0..191
    float m = g_mask[t];
    int idx = g_idx[t];
    const float4* q4 = reinterpret_cast<const float4*>(cb + (size_t)idx * CDIM);
    const float4* x4 = reinterpret_cast<const float4*>(in + (size_t)t * CDIM);
    float4* o4 = reinterpret_cast<float4*>(out + (size_t)t * CDIM);
    float4 q = q4[c4];
    float4 x = x4[c4];
    o4[c4] = make_float4(fmaf(x.x, m, q.x), fmaf(x.y, m, q.y),
                         fmaf(x.z, m, q.z), fmaf(x.w, m, q.w));
}

// ---------------------------------------------------------------------------
extern "C" void kernel_launch(void* const* d_in, const int* in_sizes, int n_in,
                              void* d_out, int out_size) {
    const float* in_feas  = (const float*)d_in[0];   // [B, L, C]
    const float* codebook = (const float*)d_in[1];   // [K, C]
    const float* att_w    = (const float*)d_in[2];   // [1, C, 3]
    float* out = (float*)d_out;
    (void)in_sizes; (void)n_in;

    int write_idx = (out_size >= MTOT * CDIM + MTOT) ? 1 : 0;
    float* out_idx_f = out + (size_t)MTOT * CDIM;

    cudaFuncSetAttribute(vq_hmma_kernel,
                         cudaFuncAttributeMaxDynamicSharedMemorySize, SMEM_B);

    {
        int n4 = MTOT * CDIM / 4;   // 9,633,792
        convert_A_kernel<<<(n4 + 255) / 256, 256>>>(in_feas, n4);
    }
    {
        int n4 = KCODE * CDIM / 4;  // 393,216
        convert_B_kernel<<<(n4 + 255) / 256, 256>>>(codebook, n4);
    }
    codenorm_kernel<<<KCODE, 256>>>(codebook);

    vq_hmma_kernel<<<MTOT / 128, 256, SMEM_B>>>();
    refine_kernel<<<(MTOT * 32 + 255) / 256, 256>>>(in_feas, codebook);

    att_kernel<<<(MTOT * 32 + 255) / 256, 256>>>(codebook, att_w, out_idx_f, write_idx);
    softmax_kernel<<<BATCH, 256>>>();
    out_kernel<<<MTOT, CDIM / 4>>>(in_feas, codebook, out);
}